// round 10
// baseline (speedup 1.0000x reference)
#include <cuda_runtime.h>
#include <math.h>

#define MAXN 20000
#define MAXE 320000

// ---- scratch (static device globals; referenced ONLY from device code) ----
__device__ float g_x[4][MAXN * 64];   // x_all slices: h, out1, out2, out3
__device__ float g_q[MAXN * 64];
__device__ float g_k[MAXN * 192];     // [node][slice(3)][64]
__device__ float g_v[MAXN * 192];
__device__ int   g_cnt[MAXN];
__device__ int   g_cur[MAXN];
__device__ int   g_off[MAXN + 1];
__device__ float g_dinv[MAXN];
__device__ int   g_src[MAXE];

// ---------------- CSR build ----------------
__global__ void k_zero(int n) {
    int i = blockIdx.x * blockDim.x + threadIdx.x;
    if (i < n) g_cnt[i] = 0;
}

__global__ void k_hist(const int* __restrict__ ei, int E) {
    int e = blockIdx.x * blockDim.x + threadIdx.x;
    if (e < E) atomicAdd(&g_cnt[ei[E + e]], 1);
}

// single-block exclusive scan of g_cnt -> g_off (+ cursor copy, + dinv)
__global__ void k_scan(int n) {
    __shared__ int ssum[1024];
    int tid = threadIdx.x;
    int chunk = (n + 1023) >> 10;
    int beg = tid * chunk;
    int end = min(beg + chunk, n);
    int s = 0;
    for (int i = beg; i < end; i++) s += g_cnt[i];
    ssum[tid] = s;
    __syncthreads();
    for (int d = 1; d < 1024; d <<= 1) {
        int v = (tid >= d) ? ssum[tid - d] : 0;
        __syncthreads();
        ssum[tid] += v;
        __syncthreads();
    }
    int run = ssum[tid] - s;   // exclusive prefix
    for (int i = beg; i < end; i++) {
        g_off[i] = run;
        g_cur[i] = run;
        g_dinv[i] = rsqrtf((float)(g_cnt[i] + 1));  // +1 self-loop
        run += g_cnt[i];
    }
    if (tid == 1023) g_off[n] = ssum[1023];
}

__global__ void k_scatter(const int* __restrict__ ei, int E) {
    int e = blockIdx.x * blockDim.x + threadIdx.x;
    if (e < E) {
        int dst = ei[E + e];
        int p = atomicAdd(&g_cur[dst], 1);
        g_src[p] = ei[e];
    }
}

// ---------------- lin1: h = relu(x @ W1 + b1), 256 -> 64 ----------------
__global__ void k_lin1(const float* __restrict__ x, const float* __restrict__ W,
                       const float* __restrict__ b, int n) {
    __shared__ float xs[16][256];
    int tx = threadIdx.x & 63;     // output col
    int ty = threadIdx.x >> 6;     // 0..3
    int base = blockIdx.x * 16;
    for (int i = threadIdx.x; i < 16 * 64; i += 256) {
        int r = i >> 6, c4 = i & 63;
        int node = base + r;
        float4 vv = (node < n) ? ((const float4*)(x + (size_t)node * 256))[c4]
                               : make_float4(0.f, 0.f, 0.f, 0.f);
        ((float4*)xs[r])[c4] = vv;
    }
    __syncthreads();
    float bias = b[tx];
    float acc[4] = {bias, bias, bias, bias};
    #pragma unroll 4
    for (int k = 0; k < 256; k++) {
        float wv = W[k * 64 + tx];
        #pragma unroll
        for (int j = 0; j < 4; j++) acc[j] += xs[ty * 4 + j][k] * wv;
    }
    #pragma unroll
    for (int j = 0; j < 4; j++) {
        int node = base + ty * 4 + j;
        if (node < n) g_x[0][node * 64 + tx] = fmaxf(acc[j], 0.f);
    }
}

// ------- fused per-layer QKV projection -------
// grid = (ceil(n/64), T+1), 512 threads.
// blockIdx.y = s < T : compute K_s and V_s (half the threads each) from g_x[s]
// blockIdx.y = T     : compute Q from g_x[T-1]
__global__ void k_qkv(const float* __restrict__ Wq, const float* __restrict__ Bq,
                      const float* __restrict__ Wk, const float* __restrict__ Bk,
                      const float* __restrict__ Wv, const float* __restrict__ Bv,
                      int T, int n) {
    __shared__ float xs[64][64];
    int s = blockIdx.y;
    int base = blockIdx.x * 64;
    const float* in = g_x[(s < T) ? s : (T - 1)];

    // cooperative load of 64 input rows (float4), shared by K and V halves
    for (int i = threadIdx.x; i < 64 * 16; i += 512) {
        int r = i >> 4, c4 = i & 15;
        int node = base + r;
        float4 vv = (node < n) ? ((const float4*)(in + (size_t)node * 64))[c4]
                               : make_float4(0.f, 0.f, 0.f, 0.f);
        ((float4*)xs[r])[c4] = vv;
    }
    __syncthreads();

    if (s < T) {
        int half = threadIdx.x >> 8;          // 0: K, 1: V
        int tx = threadIdx.x & 63;            // output col
        int ty = (threadIdx.x >> 6) & 3;      // 0..3 row groups
        const float* W = half ? Wv : Wk;
        const float* B = half ? Bv : Bk;
        float* out = (half ? g_v : g_k) + s * 64;
        float w[64];
        #pragma unroll
        for (int k = 0; k < 64; k++) w[k] = W[k * 64 + tx];
        float bias = B[tx];
        for (int j = ty; j < 64; j += 4) {
            int node = base + j;
            if (node >= n) break;
            float acc = bias;
            #pragma unroll
            for (int kq = 0; kq < 16; kq++) {
                float4 xv = ((const float4*)xs[j])[kq];   // broadcast LDS.128
                acc += xv.x * w[4*kq] + xv.y * w[4*kq+1] + xv.z * w[4*kq+2] + xv.w * w[4*kq+3];
            }
            out[(size_t)node * 192 + tx] = acc;
        }
    } else {
        int tx = threadIdx.x & 63;
        int ty = threadIdx.x >> 6;            // 0..7 row groups
        float w[64];
        #pragma unroll
        for (int k = 0; k < 64; k++) w[k] = Wq[k * 64 + tx];
        float bias = Bq[tx];
        for (int j = ty; j < 64; j += 8) {
            int node = base + j;
            if (node >= n) break;
            float acc = bias;
            #pragma unroll
            for (int kq = 0; kq < 16; kq++) {
                float4 xv = ((const float4*)xs[j])[kq];
                acc += xv.x * w[4*kq] + xv.y * w[4*kq+1] + xv.z * w[4*kq+2] + xv.w * w[4*kq+3];
            }
            g_q[(size_t)node * 64 + tx] = acc;
        }
    }
}

// -------- edge attention + aggregation: warp per destination node --------
// lane owns dims (2*lane, 2*lane+1); head = lane/4 (8 heads x 8 dims).
// Writes relu(result) into g_x[T].
template <int T>
__global__ void k_gather(int n) {
    int gw = (blockIdx.x * blockDim.x + threadIdx.x) >> 5;
    int lane = threadIdx.x & 31;
    if (gw >= n) return;
    int dst = gw;
    const float inv_sqrt_d = 0.3535533905932738f;  // 1/sqrt(8)
    float2 q2 = ((const float2*)(g_q + (size_t)dst * 64))[lane];
    float did = g_dinv[dst];
    int e0 = g_off[dst], e1 = g_off[dst + 1];
    float2 acc = make_float2(0.f, 0.f);
    for (int e = e0; e <= e1; e++) {          // e == e1 -> self-loop edge
        int src = (e < e1) ? __ldg(&g_src[e]) : dst;
        float sdi = g_dinv[src];
        const float2* kp = (const float2*)(g_k + (size_t)src * 192);
        const float2* vp = (const float2*)(g_v + (size_t)src * 192);
        float2 kk[T], vv[T];
        #pragma unroll
        for (int s = 0; s < T; s++) { kk[s] = kp[s * 32 + lane]; vv[s] = vp[s * 32 + lane]; }
        float sc[T];
        float mx = -1e30f;
        #pragma unroll
        for (int s = 0; s < T; s++) {
            float p = q2.x * kk[s].x + q2.y * kk[s].y;
            p += __shfl_xor_sync(0xffffffffu, p, 1);
            p += __shfl_xor_sync(0xffffffffu, p, 2);   // head-group (4 lanes) dot
            sc[s] = p * inv_sqrt_d;
            mx = fmaxf(mx, sc[s]);
        }
        float sum = 0.f;
        #pragma unroll
        for (int s = 0; s < T; s++) { sc[s] = __expf(sc[s] - mx); sum += sc[s]; }
        float scale = __fdividef(sdi, sum);   // norm_e = dinv[src]*dinv[dst]; dst part at end
        float2 m = make_float2(0.f, 0.f);
        #pragma unroll
        for (int s = 0; s < T; s++) { m.x += sc[s] * vv[s].x; m.y += sc[s] * vv[s].y; }
        acc.x += m.x * scale;
        acc.y += m.y * scale;
    }
    float2 o;
    o.x = fmaxf(acc.x * did, 0.f);
    o.y = fmaxf(acc.y * did, 0.f);
    ((float2*)(g_x[T] + (size_t)dst * 64))[lane] = o;
}

// ---------------- lin2 + log_softmax: warp per node, reads g_x[3] ----------------
__global__ void k_lin2_ls(const float* __restrict__ W, const float* __restrict__ b,
                          float* __restrict__ out, int n) {
    int gw = (blockIdx.x * blockDim.x + threadIdx.x) >> 5;
    int lane = threadIdx.x & 31;
    if (gw >= n) return;
    const float* hr = g_x[3] + (size_t)gw * 64;
    float2 acc = ((const float2*)b)[lane];
    #pragma unroll 8
    for (int k = 0; k < 64; k++) {
        float hk = hr[k];
        float2 w2 = ((const float2*)(W + k * 64))[lane];
        acc.x += hk * w2.x;
        acc.y += hk * w2.y;
    }
    float m = fmaxf(acc.x, acc.y);
    #pragma unroll
    for (int o = 16; o > 0; o >>= 1) m = fmaxf(m, __shfl_xor_sync(0xffffffffu, m, o));
    float se = __expf(acc.x - m) + __expf(acc.y - m);
    #pragma unroll
    for (int o = 16; o > 0; o >>= 1) se += __shfl_xor_sync(0xffffffffu, se, o);
    float lse = m + logf(se);
    float2 r;
    r.x = acc.x - lse;
    r.y = acc.y - lse;
    ((float2*)(out + (size_t)gw * 64))[lane] = r;
}

// ---------------- host launcher (kernel launches ONLY) ----------------
extern "C" void kernel_launch(void* const* d_in, const int* in_sizes, int n_in,
                              void* d_out, int out_size) {
    const float* x  = (const float*)d_in[0];
    const int*   ei = (const int*)d_in[1];     // int32 (JAX default int without x64)
    const float* w1 = (const float*)d_in[2];
    const float* b1 = (const float*)d_in[3];
    const float* wq = (const float*)d_in[4];
    const float* bq = (const float*)d_in[5];
    const float* wk = (const float*)d_in[6];
    const float* bk = (const float*)d_in[7];
    const float* wv = (const float*)d_in[8];
    const float* bv = (const float*)d_in[9];
    const float* w2 = (const float*)d_in[10];
    const float* b2 = (const float*)d_in[11];

    int n = in_sizes[0] / 256;   // IN_C = 256
    int E = in_sizes[1] / 2;

    // CSR by destination (+ degrees/dinv)           // launches 1..4
    k_zero<<<(n + 255) / 256, 256>>>(n);
    k_hist<<<(E + 255) / 256, 256>>>(ei, E);
    k_scan<<<1, 1024>>>(n);
    k_scatter<<<(E + 255) / 256, 256>>>(ei, E);

    // input projection -> g_x[0]                    // launch 5
    k_lin1<<<(n + 15) / 16, 256>>>(x, w1, b1, n);

    int gB64 = (n + 63) / 64;
    int gWarp = (n * 32 + 255) / 256;
    for (int l = 0; l < 3; l++) {
        int t = l + 1;
        dim3 grid(gB64, t + 1);
        k_qkv<<<grid, 512>>>(wq + l * 4096, bq + l * 64,
                             wk + l * 4096, bk + l * 64,
                             wv + l * 4096, bv + l * 64, t, n);
        if (t == 1)      k_gather<1><<<gWarp, 256>>>(n);
        else if (t == 2) k_gather<2><<<gWarp, 256>>>(n);
        else             k_gather<3><<<gWarp, 256>>>(n);
    }

    k_lin2_ls<<<gWarp, 256>>>(w2, b2, (float*)d_out, n);
}

// round 11
// speedup vs baseline: 1.3313x; 1.3313x over previous
#include <cuda_runtime.h>
#include <cuda_fp16.h>
#include <math.h>

#define MAXN 20000
#define MAXE 320000

// ---- scratch (static device globals; referenced ONLY from device code) ----
__device__ float  g_x[4][MAXN * 64];   // x_all slices: h, out1, out2, out3 (fp32)
__device__ __half g_qh[MAXN * 64];
__device__ __half g_kh[MAXN * 192];    // [node][slice(3)][64]
__device__ __half g_vh[MAXN * 192];
__device__ int    g_cnt[MAXN];
__device__ int    g_cur[MAXN];
__device__ int    g_off[MAXN + 1];
__device__ float  g_dinv[MAXN];
__device__ int    g_src[MAXE];

// ---------------- CSR build ----------------
__global__ void k_zero(int n) {
    int i = blockIdx.x * blockDim.x + threadIdx.x;
    if (i < n) g_cnt[i] = 0;
}

__global__ void k_hist(const int* __restrict__ ei, int E) {
    int e = blockIdx.x * blockDim.x + threadIdx.x;
    if (e < E) atomicAdd(&g_cnt[ei[E + e]], 1);
}

// single-block exclusive scan of g_cnt -> g_off (+ cursor copy, + dinv)
__global__ void k_scan(int n) {
    __shared__ int ssum[1024];
    int tid = threadIdx.x;
    int chunk = (n + 1023) >> 10;
    int beg = tid * chunk;
    int end = min(beg + chunk, n);
    int s = 0;
    for (int i = beg; i < end; i++) s += g_cnt[i];
    ssum[tid] = s;
    __syncthreads();
    for (int d = 1; d < 1024; d <<= 1) {
        int v = (tid >= d) ? ssum[tid - d] : 0;
        __syncthreads();
        ssum[tid] += v;
        __syncthreads();
    }
    int run = ssum[tid] - s;   // exclusive prefix
    for (int i = beg; i < end; i++) {
        g_off[i] = run;
        g_cur[i] = run;
        g_dinv[i] = rsqrtf((float)(g_cnt[i] + 1));  // +1 self-loop
        run += g_cnt[i];
    }
    if (tid == 1023) g_off[n] = ssum[1023];
}

__global__ void k_scatter(const int* __restrict__ ei, int E) {
    int e = blockIdx.x * blockDim.x + threadIdx.x;
    if (e < E) {
        int dst = ei[E + e];
        int p = atomicAdd(&g_cur[dst], 1);
        g_src[p] = ei[e];
    }
}

// ---------------- lin1: h = relu(x @ W1 + b1), 256 -> 64 (fp32) ----------------
__global__ void k_lin1(const float* __restrict__ x, const float* __restrict__ W,
                       const float* __restrict__ b, int n) {
    __shared__ float xs[16][256];
    int tx = threadIdx.x & 63;     // output col
    int ty = threadIdx.x >> 6;     // 0..3
    int base = blockIdx.x * 16;
    for (int i = threadIdx.x; i < 16 * 64; i += 256) {
        int r = i >> 6, c4 = i & 63;
        int node = base + r;
        float4 vv = (node < n) ? ((const float4*)(x + (size_t)node * 256))[c4]
                               : make_float4(0.f, 0.f, 0.f, 0.f);
        ((float4*)xs[r])[c4] = vv;
    }
    __syncthreads();
    float bias = b[tx];
    float acc[4] = {bias, bias, bias, bias};
    #pragma unroll 4
    for (int k = 0; k < 256; k++) {
        float wv = W[k * 64 + tx];
        #pragma unroll
        for (int j = 0; j < 4; j++) acc[j] += xs[ty * 4 + j][k] * wv;
    }
    #pragma unroll
    for (int j = 0; j < 4; j++) {
        int node = base + ty * 4 + j;
        if (node < n) g_x[0][node * 64 + tx] = fmaxf(acc[j], 0.f);
    }
}

// ------- 64x64 GEMM, fp32 compute, fp16 output -------
// dst_kind: 0 -> g_qh (stride 64), 1 -> g_kh + s*64 (stride 192), 2 -> g_vh + s*64
__global__ void k_gemm64(const float* __restrict__ W, const float* __restrict__ b,
                         int in_slice, int dst_kind, int out_slice, int n) {
    __shared__ float xs[64][64];
    int tx = threadIdx.x & 63;     // output col
    int ty = threadIdx.x >> 6;     // 0..3
    int base = blockIdx.x * 64;

    const float* in = g_x[in_slice];
    __half* out;
    int ostride;
    if (dst_kind == 0)      { out = g_qh;                   ostride = 64;  }
    else if (dst_kind == 1) { out = g_kh + out_slice * 64;  ostride = 192; }
    else                    { out = g_vh + out_slice * 64;  ostride = 192; }

    float w[64];
    #pragma unroll
    for (int k = 0; k < 64; k++) w[k] = W[k * 64 + tx];  // W column in regs
    for (int i = threadIdx.x; i < 64 * 16; i += 256) {   // 64 rows x 16 float4
        int r = i >> 4, c4 = i & 15;
        int node = base + r;
        float4 vv = (node < n) ? ((const float4*)(in + (size_t)node * 64))[c4]
                               : make_float4(0.f, 0.f, 0.f, 0.f);
        ((float4*)xs[r])[c4] = vv;
    }
    __syncthreads();
    float bias = b[tx];
    for (int j = ty; j < 64; j += 4) {
        int node = base + j;
        if (node >= n) break;
        float acc = bias;
        #pragma unroll
        for (int kq = 0; kq < 16; kq++) {
            float4 xv = ((const float4*)xs[j])[kq];   // broadcast LDS.128
            acc += xv.x * w[4*kq] + xv.y * w[4*kq+1] + xv.z * w[4*kq+2] + xv.w * w[4*kq+3];
        }
        out[(size_t)node * ostride + tx] = __float2half_rn(acc);
    }
}

// -------- edge attention + aggregation: warp per destination node --------
// lane owns dims (2*lane, 2*lane+1); head = lane/4 (8 heads x 8 dims).
// fp16 q/k/v loads, fp32 math. Writes relu(result) into g_x[T].
template <int T>
__global__ void k_gather(int n) {
    int gw = (blockIdx.x * blockDim.x + threadIdx.x) >> 5;
    int lane = threadIdx.x & 31;
    if (gw >= n) return;
    int dst = gw;
    const float inv_sqrt_d = 0.3535533905932738f;  // 1/sqrt(8)
    float2 q2 = __half22float2(((const __half2*)(g_qh + (size_t)dst * 64))[lane]);
    float did = g_dinv[dst];
    int e0 = g_off[dst], e1 = g_off[dst + 1];
    float2 acc = make_float2(0.f, 0.f);
    for (int e = e0; e <= e1; e++) {          // e == e1 -> self-loop edge
        int src = (e < e1) ? __ldg(&g_src[e]) : dst;
        float sdi = g_dinv[src];
        const __half2* kp = (const __half2*)(g_kh + (size_t)src * 192);
        const __half2* vp = (const __half2*)(g_vh + (size_t)src * 192);
        float2 kk[T], vv[T];
        #pragma unroll
        for (int s = 0; s < T; s++) {
            kk[s] = __half22float2(kp[s * 32 + lane]);
            vv[s] = __half22float2(vp[s * 32 + lane]);
        }
        float sc[T];
        float mx = -1e30f;
        #pragma unroll
        for (int s = 0; s < T; s++) {
            float p = q2.x * kk[s].x + q2.y * kk[s].y;
            p += __shfl_xor_sync(0xffffffffu, p, 1);
            p += __shfl_xor_sync(0xffffffffu, p, 2);   // head-group (4 lanes) dot
            sc[s] = p * inv_sqrt_d;
            mx = fmaxf(mx, sc[s]);
        }
        float sum = 0.f;
        #pragma unroll
        for (int s = 0; s < T; s++) { sc[s] = __expf(sc[s] - mx); sum += sc[s]; }
        float scale = __fdividef(sdi, sum);   // norm_e = dinv[src]*dinv[dst]; dst part at end
        float2 m = make_float2(0.f, 0.f);
        #pragma unroll
        for (int s = 0; s < T; s++) { m.x += sc[s] * vv[s].x; m.y += sc[s] * vv[s].y; }
        acc.x += m.x * scale;
        acc.y += m.y * scale;
    }
    float2 o;
    o.x = fmaxf(acc.x * did, 0.f);
    o.y = fmaxf(acc.y * did, 0.f);
    ((float2*)(g_x[T] + (size_t)dst * 64))[lane] = o;
}

// ---------------- lin2 + log_softmax: warp per node, reads g_x[3] ----------------
__global__ void k_lin2_ls(const float* __restrict__ W, const float* __restrict__ b,
                          float* __restrict__ out, int n) {
    int gw = (blockIdx.x * blockDim.x + threadIdx.x) >> 5;
    int lane = threadIdx.x & 31;
    if (gw >= n) return;
    const float* hr = g_x[3] + (size_t)gw * 64;
    float2 acc = ((const float2*)b)[lane];
    #pragma unroll 8
    for (int k = 0; k < 64; k++) {
        float hk = hr[k];
        float2 w2 = ((const float2*)(W + k * 64))[lane];
        acc.x += hk * w2.x;
        acc.y += hk * w2.y;
    }
    float m = fmaxf(acc.x, acc.y);
    #pragma unroll
    for (int o = 16; o > 0; o >>= 1) m = fmaxf(m, __shfl_xor_sync(0xffffffffu, m, o));
    float se = __expf(acc.x - m) + __expf(acc.y - m);
    #pragma unroll
    for (int o = 16; o > 0; o >>= 1) se += __shfl_xor_sync(0xffffffffu, se, o);
    float lse = m + logf(se);
    float2 r;
    r.x = acc.x - lse;
    r.y = acc.y - lse;
    ((float2*)(out + (size_t)gw * 64))[lane] = r;
}

// ---------------- host launcher (kernel launches ONLY) ----------------
extern "C" void kernel_launch(void* const* d_in, const int* in_sizes, int n_in,
                              void* d_out, int out_size) {
    const float* x  = (const float*)d_in[0];
    const int*   ei = (const int*)d_in[1];     // int32 (JAX default int without x64)
    const float* w1 = (const float*)d_in[2];
    const float* b1 = (const float*)d_in[3];
    const float* wq = (const float*)d_in[4];
    const float* bq = (const float*)d_in[5];
    const float* wk = (const float*)d_in[6];
    const float* bk = (const float*)d_in[7];
    const float* wv = (const float*)d_in[8];
    const float* bv = (const float*)d_in[9];
    const float* w2 = (const float*)d_in[10];
    const float* b2 = (const float*)d_in[11];

    int n = in_sizes[0] / 256;   // IN_C = 256
    int E = in_sizes[1] / 2;

    // CSR by destination (+ degrees/dinv)
    k_zero<<<(n + 255) / 256, 256>>>(n);
    k_hist<<<(E + 255) / 256, 256>>>(ei, E);
    k_scan<<<1, 1024>>>(n);
    k_scatter<<<(E + 255) / 256, 256>>>(ei, E);

    // input projection -> g_x[0]
    k_lin1<<<(n + 15) / 16, 256>>>(x, w1, b1, n);

    int gB64 = (n + 63) / 64;
    int gWarp = (n * 32 + 255) / 256;
    for (int l = 0; l < 3; l++) {
        int t = l + 1;
        const float* Wq = wq + l * 4096; const float* Bq = bq + l * 64;
        const float* Wk = wk + l * 4096; const float* Bk = bk + l * 64;
        const float* Wv = wv + l * 4096; const float* Bv = bv + l * 64;
        // q from last slice
        k_gemm64<<<gB64, 256>>>(Wq, Bq, t - 1, 0, 0, n);
        // k, v for all slices
        for (int s = 0; s < t; s++) {
            k_gemm64<<<gB64, 256>>>(Wk, Bk, s, 1, s, n);
            k_gemm64<<<gB64, 256>>>(Wv, Bv, s, 2, s, n);
        }
        if (t == 1)      k_gather<1><<<gWarp, 256>>>(n);
        else if (t == 2) k_gather<2><<<gWarp, 256>>>(n);
        else             k_gather<3><<<gWarp, 256>>>(n);
    }

    k_lin2_ls<<<gWarp, 256>>>(w2, b2, (float*)d_out, n);
}

// round 12
// speedup vs baseline: 1.5494x; 1.1638x over previous
#include <cuda_runtime.h>
#include <cuda_fp16.h>
#include <math.h>

#define MAXN 20000
#define MAXE 320000

// ---- scratch (static device globals; referenced ONLY from device code) ----
__device__ float  g_x[4][MAXN * 64];   // x_all slices: h, out1, out2, out3 (fp32)
__device__ __half g_qh[MAXN * 64];
__device__ __half g_kh[MAXN * 192];    // [node][slice(3)][64]
__device__ __half g_vh[MAXN * 192];
__device__ int    g_cnt[MAXN];
__device__ int    g_cur[MAXN];
__device__ int    g_off[MAXN + 1];
__device__ float  g_dinv[MAXN];
__device__ int    g_src[MAXE];

// ---------------- CSR build ----------------
__global__ void k_zero(int n) {
    int i = blockIdx.x * blockDim.x + threadIdx.x;
    if (i < n) g_cnt[i] = 0;
}

__global__ void k_hist(const int* __restrict__ ei, int E) {
    int e = blockIdx.x * blockDim.x + threadIdx.x;
    if (e < E) atomicAdd(&g_cnt[ei[E + e]], 1);
}

// single-block exclusive scan of g_cnt -> g_off (+ cursor copy, + dinv)
__global__ void k_scan(int n) {
    __shared__ int ssum[1024];
    int tid = threadIdx.x;
    int chunk = (n + 1023) >> 10;
    int beg = tid * chunk;
    int end = min(beg + chunk, n);
    int s = 0;
    for (int i = beg; i < end; i++) s += g_cnt[i];
    ssum[tid] = s;
    __syncthreads();
    for (int d = 1; d < 1024; d <<= 1) {
        int v = (tid >= d) ? ssum[tid - d] : 0;
        __syncthreads();
        ssum[tid] += v;
        __syncthreads();
    }
    int run = ssum[tid] - s;   // exclusive prefix
    for (int i = beg; i < end; i++) {
        g_off[i] = run;
        g_cur[i] = run;
        g_dinv[i] = rsqrtf((float)(g_cnt[i] + 1));  // +1 self-loop
        run += g_cnt[i];
    }
    if (tid == 1023) g_off[n] = ssum[1023];
}

__global__ void k_scatter(const int* __restrict__ ei, int E) {
    int e = blockIdx.x * blockDim.x + threadIdx.x;
    if (e < E) {
        int dst = ei[E + e];
        int p = atomicAdd(&g_cur[dst], 1);
        g_src[p] = ei[e];
    }
}

// ---------------- lin1: h = relu(x @ W1 + b1), 256 -> 64 (fp32) ----------------
__global__ void k_lin1(const float* __restrict__ x, const float* __restrict__ W,
                       const float* __restrict__ b, int n) {
    __shared__ float xs[16][256];
    int tx = threadIdx.x & 63;     // output col
    int ty = threadIdx.x >> 6;     // 0..3
    int base = blockIdx.x * 16;
    for (int i = threadIdx.x; i < 16 * 64; i += 256) {
        int r = i >> 6, c4 = i & 63;
        int node = base + r;
        float4 vv = (node < n) ? ((const float4*)(x + (size_t)node * 256))[c4]
                               : make_float4(0.f, 0.f, 0.f, 0.f);
        ((float4*)xs[r])[c4] = vv;
    }
    __syncthreads();
    float bias = b[tx];
    float acc[4] = {bias, bias, bias, bias};
    #pragma unroll 4
    for (int k = 0; k < 256; k++) {
        float wv = W[k * 64 + tx];
        #pragma unroll
        for (int j = 0; j < 4; j++) acc[j] += xs[ty * 4 + j][k] * wv;
    }
    #pragma unroll
    for (int j = 0; j < 4; j++) {
        int node = base + ty * 4 + j;
        if (node < n) g_x[0][node * 64 + tx] = fmaxf(acc[j], 0.f);
    }
}

// ------- per-layer QKV projections, one launch -------
// grid = (ceil(n/64), 2T+1), 256 threads; identical per-block shape to old k_gemm64.
// blockIdx.y: 0 -> Q (from g_x[T-1]); 1..T -> K_{y-1}; T+1..2T -> V_{y-T-1}
__global__ void k_qkv(const float* __restrict__ Wq, const float* __restrict__ Bq,
                      const float* __restrict__ Wk, const float* __restrict__ Bk,
                      const float* __restrict__ Wv, const float* __restrict__ Bv,
                      int T, int n) {
    __shared__ float xs[64][64];
    int tx = threadIdx.x & 63;     // output col
    int ty = threadIdx.x >> 6;     // 0..3
    int base = blockIdx.x * 64;
    int job = blockIdx.y;

    const float* W; const float* B; const float* in; __half* out; int ostride;
    if (job == 0)      { W = Wq; B = Bq; in = g_x[T - 1];       out = g_qh;                      ostride = 64;  }
    else if (job <= T) { W = Wk; B = Bk; in = g_x[job - 1];     out = g_kh + (job - 1) * 64;     ostride = 192; }
    else               { W = Wv; B = Bv; in = g_x[job - T - 1]; out = g_vh + (job - T - 1) * 64; ostride = 192; }

    float w[64];
    #pragma unroll
    for (int k = 0; k < 64; k++) w[k] = W[k * 64 + tx];  // W column in regs
    for (int i = threadIdx.x; i < 64 * 16; i += 256) {   // 64 rows x 16 float4
        int r = i >> 4, c4 = i & 15;
        int node = base + r;
        float4 vv = (node < n) ? ((const float4*)(in + (size_t)node * 64))[c4]
                               : make_float4(0.f, 0.f, 0.f, 0.f);
        ((float4*)xs[r])[c4] = vv;
    }
    __syncthreads();
    float bias = B[tx];
    for (int j = ty; j < 64; j += 4) {
        int node = base + j;
        if (node >= n) break;
        float acc = bias;
        #pragma unroll
        for (int kq = 0; kq < 16; kq++) {
            float4 xv = ((const float4*)xs[j])[kq];   // broadcast LDS.128
            acc += xv.x * w[4*kq] + xv.y * w[4*kq+1] + xv.z * w[4*kq+2] + xv.w * w[4*kq+3];
        }
        out[(size_t)node * ostride + tx] = __float2half_rn(acc);
    }
}

// -------- edge attention + aggregation: warp per destination node --------
// lane owns dims (2*lane, 2*lane+1); head = lane/4 (8 heads x 8 dims).
// Edge indices batch-loaded (one coalesced LDG per 32 edges) and shfl-broadcast.
template <int T>
__global__ void k_gather(int n) {
    int gw = (blockIdx.x * blockDim.x + threadIdx.x) >> 5;
    int lane = threadIdx.x & 31;
    if (gw >= n) return;
    int dst = gw;
    const float inv_sqrt_d = 0.3535533905932738f;  // 1/sqrt(8)
    float2 q2 = __half22float2(((const __half2*)(g_qh + (size_t)dst * 64))[lane]);
    float did = g_dinv[dst];
    int e0 = g_off[dst], e1 = g_off[dst + 1];
    int tot = e1 - e0 + 1;                 // + self-loop
    float2 acc = make_float2(0.f, 0.f);
    for (int base = 0; base < tot; base += 32) {
        int idx = e0 + base + lane;
        int mysrc = (idx < e1) ? g_src[idx] : dst;   // idx==e1 -> self-loop
        int cnt = min(32, tot - base);
        for (int j = 0; j < cnt; j++) {
            int src = __shfl_sync(0xffffffffu, mysrc, j);
            float sdi = g_dinv[src];
            const __half2* kp = (const __half2*)(g_kh + (size_t)src * 192);
            const __half2* vp = (const __half2*)(g_vh + (size_t)src * 192);
            float2 kk[T], vv[T];
            #pragma unroll
            for (int s = 0; s < T; s++) {
                kk[s] = __half22float2(kp[s * 32 + lane]);
                vv[s] = __half22float2(vp[s * 32 + lane]);
            }
            float sc[T];
            float mx = -1e30f;
            #pragma unroll
            for (int s = 0; s < T; s++) {
                float p = q2.x * kk[s].x + q2.y * kk[s].y;
                p += __shfl_xor_sync(0xffffffffu, p, 1);
                p += __shfl_xor_sync(0xffffffffu, p, 2);   // head-group (4 lanes) dot
                sc[s] = p * inv_sqrt_d;
                mx = fmaxf(mx, sc[s]);
            }
            float sum = 0.f;
            #pragma unroll
            for (int s = 0; s < T; s++) { sc[s] = __expf(sc[s] - mx); sum += sc[s]; }
            float scale = __fdividef(sdi, sum);
            float2 m = make_float2(0.f, 0.f);
            #pragma unroll
            for (int s = 0; s < T; s++) { m.x += sc[s] * vv[s].x; m.y += sc[s] * vv[s].y; }
            acc.x += m.x * scale;
            acc.y += m.y * scale;
        }
    }
    float2 o;
    o.x = fmaxf(acc.x * did, 0.f);
    o.y = fmaxf(acc.y * did, 0.f);
    ((float2*)(g_x[T] + (size_t)dst * 64))[lane] = o;
}

// ---------------- lin2 + log_softmax: warp per node, reads g_x[3] ----------------
__global__ void k_lin2_ls(const float* __restrict__ W, const float* __restrict__ b,
                          float* __restrict__ out, int n) {
    int gw = (blockIdx.x * blockDim.x + threadIdx.x) >> 5;
    int lane = threadIdx.x & 31;
    if (gw >= n) return;
    const float* hr = g_x[3] + (size_t)gw * 64;
    float2 acc = ((const float2*)b)[lane];
    #pragma unroll 8
    for (int k = 0; k < 64; k++) {
        float hk = hr[k];
        float2 w2 = ((const float2*)(W + k * 64))[lane];
        acc.x += hk * w2.x;
        acc.y += hk * w2.y;
    }
    float m = fmaxf(acc.x, acc.y);
    #pragma unroll
    for (int o = 16; o > 0; o >>= 1) m = fmaxf(m, __shfl_xor_sync(0xffffffffu, m, o));
    float se = __expf(acc.x - m) + __expf(acc.y - m);
    #pragma unroll
    for (int o = 16; o > 0; o >>= 1) se += __shfl_xor_sync(0xffffffffu, se, o);
    float lse = m + logf(se);
    float2 r;
    r.x = acc.x - lse;
    r.y = acc.y - lse;
    ((float2*)(out + (size_t)gw * 64))[lane] = r;
}

// ---------------- host launcher (kernel launches ONLY) ----------------
extern "C" void kernel_launch(void* const* d_in, const int* in_sizes, int n_in,
                              void* d_out, int out_size) {
    const float* x  = (const float*)d_in[0];
    const int*   ei = (const int*)d_in[1];     // int32 (JAX default int without x64)
    const float* w1 = (const float*)d_in[2];
    const float* b1 = (const float*)d_in[3];
    const float* wq = (const float*)d_in[4];
    const float* bq = (const float*)d_in[5];
    const float* wk = (const float*)d_in[6];
    const float* bk = (const float*)d_in[7];
    const float* wv = (const float*)d_in[8];
    const float* bv = (const float*)d_in[9];
    const float* w2 = (const float*)d_in[10];
    const float* b2 = (const float*)d_in[11];

    int n = in_sizes[0] / 256;   // IN_C = 256
    int E = in_sizes[1] / 2;

    // CSR by destination (+ degrees/dinv)
    k_zero<<<(n + 255) / 256, 256>>>(n);
    k_hist<<<(E + 255) / 256, 256>>>(ei, E);
    k_scan<<<1, 1024>>>(n);
    k_scatter<<<(E + 255) / 256, 256>>>(ei, E);

    // input projection -> g_x[0]
    k_lin1<<<(n + 15) / 16, 256>>>(x, w1, b1, n);

    int gB64 = (n + 63) / 64;
    int gWarp = (n * 32 + 255) / 256;
    for (int l = 0; l < 3; l++) {
        int t = l + 1;
        dim3 grid(gB64, 2 * t + 1);
        k_qkv<<<grid, 256>>>(wq + l * 4096, bq + l * 64,
                             wk + l * 4096, bk + l * 64,
                             wv + l * 4096, bv + l * 64, t, n);
        if (t == 1)      k_gather<1><<<gWarp, 256>>>(n);
        else if (t == 2) k_gather<2><<<gWarp, 256>>>(n);
        else             k_gather<3><<<gWarp, 256>>>(n);
    }

    k_lin2_ls<<<gWarp, 256>>>(w2, b2, (float*)d_out, n);
}

// round 14
// speedup vs baseline: 2.0299x; 1.3101x over previous
#include <cuda_runtime.h>
#include <cuda_fp16.h>
#include <stdint.h>
#include <math.h>

#define MAXN 20000
#define MAXE 320000

// ---- scratch (static device globals; referenced ONLY from device code) ----
__device__ float  g_x[4][MAXN * 64];   // x_all slices: h, out1, out2, out3 (fp32)
__device__ __half g_qh[MAXN * 64];
__device__ __half g_kh[MAXN * 192];    // [node][slice(3)][64]
__device__ __half g_vh[MAXN * 192];
__device__ int    g_cnt[MAXN];
__device__ int    g_cur[MAXN];
__device__ int    g_off[MAXN + 1];
__device__ float  g_dinv[MAXN];
__device__ int    g_src[MAXE];

__device__ __forceinline__ float to_tf32(float x) {
    uint32_t u;
    asm("cvt.rna.tf32.f32 %0, %1;" : "=r"(u) : "f"(x));
    return __uint_as_float(u);
}

__device__ __forceinline__ void mma_tf32(float& d0, float& d1, float& d2, float& d3,
                                         uint32_t a0, uint32_t a1, uint32_t a2, uint32_t a3,
                                         uint32_t b0, uint32_t b1) {
    asm("mma.sync.aligned.m16n8k8.row.col.f32.tf32.tf32.f32 "
        "{%0,%1,%2,%3}, {%4,%5,%6,%7}, {%8,%9}, {%0,%1,%2,%3};"
        : "+f"(d0), "+f"(d1), "+f"(d2), "+f"(d3)
        : "r"(a0), "r"(a1), "r"(a2), "r"(a3), "r"(b0), "r"(b1));
}

// ---------------- CSR build ----------------
__global__ void k_zero(int n) {
    int i = blockIdx.x * blockDim.x + threadIdx.x;
    if (i < n) g_cnt[i] = 0;
}

__global__ void k_hist(const int* __restrict__ ei, int E) {
    int e = blockIdx.x * blockDim.x + threadIdx.x;
    if (e < E) atomicAdd(&g_cnt[ei[E + e]], 1);
}

// single-block exclusive scan of g_cnt -> g_off (+ cursor copy, + dinv)
__global__ void k_scan(int n) {
    __shared__ int ssum[1024];
    int tid = threadIdx.x;
    int chunk = (n + 1023) >> 10;
    int beg = tid * chunk;
    int end = min(beg + chunk, n);
    int s = 0;
    for (int i = beg; i < end; i++) s += g_cnt[i];
    ssum[tid] = s;
    __syncthreads();
    for (int d = 1; d < 1024; d <<= 1) {
        int v = (tid >= d) ? ssum[tid - d] : 0;
        __syncthreads();
        ssum[tid] += v;
        __syncthreads();
    }
    int run = ssum[tid] - s;   // exclusive prefix
    for (int i = beg; i < end; i++) {
        g_off[i] = run;
        g_cur[i] = run;
        g_dinv[i] = rsqrtf((float)(g_cnt[i] + 1));  // +1 self-loop
        run += g_cnt[i];
    }
    if (tid == 1023) g_off[n] = ssum[1023];
}

__global__ void k_scatter(const int* __restrict__ ei, int E) {
    int e = blockIdx.x * blockDim.x + threadIdx.x;
    if (e < E) {
        int dst = ei[E + e];
        int p = atomicAdd(&g_cur[dst], 1);
        g_src[p] = ei[e];
    }
}

// ---------------- lin1 via tf32 mma: g_x[0] = relu(x @ W1 + b1), 256->64 ----------------
// Block: 64 nodes x 64 cols, 8 warps. K=256 chunked by 64.
__global__ void k_lin1(const float* __restrict__ x, const float* __restrict__ W,
                       const float* __restrict__ b, int n) {
    __shared__ float xs[64][68];
    __shared__ float ws[64][68];
    int tid = threadIdx.x;
    int warp = tid >> 5, lane = tid & 31;
    int base = blockIdx.x * 64;
    int r0 = (warp & 3) * 16;        // warp row tile
    int c0 = (warp >> 2) * 32;       // warp col tile
    float acc[4][4] = {};

    for (int kc = 0; kc < 4; kc++) {         // K chunks of 64
        // load x chunk [64 nodes][64 k] (tf32-converted)
        for (int i = tid; i < 64 * 16; i += 256) {
            int r = i >> 4, c4 = (i & 15) * 4;
            int node = base + r;
            float4 vv = (node < n) ? ((const float4*)(x + (size_t)node * 256 + kc * 64))[i & 15]
                                   : make_float4(0.f, 0.f, 0.f, 0.f);
            xs[r][c4]     = to_tf32(vv.x);
            xs[r][c4 + 1] = to_tf32(vv.y);
            xs[r][c4 + 2] = to_tf32(vv.z);
            xs[r][c4 + 3] = to_tf32(vv.w);
        }
        // load W chunk [64 k][64 n]
        for (int i = tid; i < 64 * 16; i += 256) {
            int r = i >> 4, c4 = (i & 15) * 4;
            float4 wv = ((const float4*)(W + (size_t)(kc * 64 + r) * 64))[i & 15];
            ws[r][c4]     = to_tf32(wv.x);
            ws[r][c4 + 1] = to_tf32(wv.y);
            ws[r][c4 + 2] = to_tf32(wv.z);
            ws[r][c4 + 3] = to_tf32(wv.w);
        }
        __syncthreads();
        #pragma unroll
        for (int ks = 0; ks < 64; ks += 8) {
            uint32_t a0 = __float_as_uint(xs[r0 + (lane >> 2)][ks + (lane & 3)]);
            uint32_t a1 = __float_as_uint(xs[r0 + (lane >> 2) + 8][ks + (lane & 3)]);
            uint32_t a2 = __float_as_uint(xs[r0 + (lane >> 2)][ks + (lane & 3) + 4]);
            uint32_t a3 = __float_as_uint(xs[r0 + (lane >> 2) + 8][ks + (lane & 3) + 4]);
            #pragma unroll
            for (int nt = 0; nt < 4; nt++) {
                int nc = c0 + nt * 8;
                uint32_t b0 = __float_as_uint(ws[ks + (lane & 3)][nc + (lane >> 2)]);
                uint32_t b1 = __float_as_uint(ws[ks + (lane & 3) + 4][nc + (lane >> 2)]);
                mma_tf32(acc[nt][0], acc[nt][1], acc[nt][2], acc[nt][3], a0, a1, a2, a3, b0, b1);
            }
        }
        __syncthreads();
    }
    // epilogue: bias + relu -> g_x[0] (fp32)
    int rA = r0 + (lane >> 2), rB = rA + 8;
    #pragma unroll
    for (int nt = 0; nt < 4; nt++) {
        int c = c0 + nt * 8 + (lane & 3) * 2;
        float bx = b[c], by = b[c + 1];
        int nodeA = base + rA;
        if (nodeA < n) {
            float2 o = make_float2(fmaxf(acc[nt][0] + bx, 0.f), fmaxf(acc[nt][1] + by, 0.f));
            *(float2*)(g_x[0] + (size_t)nodeA * 64 + c) = o;
        }
        int nodeB = base + rB;
        if (nodeB < n) {
            float2 o = make_float2(fmaxf(acc[nt][2] + bx, 0.f), fmaxf(acc[nt][3] + by, 0.f));
            *(float2*)(g_x[0] + (size_t)nodeB * 64 + c) = o;
        }
    }
}

// ------- per-layer QKV projections via tf32 mma, one launch -------
// grid = (ceil(n/64), 2T+1). blockIdx.y: 0 -> Q; 1..T -> K_{y-1}; T+1..2T -> V_{y-T-1}
__global__ void k_qkv(const float* __restrict__ Wq, const float* __restrict__ Bq,
                      const float* __restrict__ Wk, const float* __restrict__ Bk,
                      const float* __restrict__ Wv, const float* __restrict__ Bv,
                      int T, int n) {
    __shared__ float xs[64][68];
    __shared__ float ws[64][68];
    int tid = threadIdx.x;
    int warp = tid >> 5, lane = tid & 31;
    int base = blockIdx.x * 64;
    int job = blockIdx.y;

    const float* W; const float* B; const float* in; __half* out; int ostride;
    if (job == 0)      { W = Wq; B = Bq; in = g_x[T - 1];       out = g_qh;                      ostride = 64;  }
    else if (job <= T) { W = Wk; B = Bk; in = g_x[job - 1];     out = g_kh + (job - 1) * 64;     ostride = 192; }
    else               { W = Wv; B = Bv; in = g_x[job - T - 1]; out = g_vh + (job - T - 1) * 64; ostride = 192; }

    // load x tile [64 nodes][64]
    for (int i = tid; i < 64 * 16; i += 256) {
        int r = i >> 4, c4 = (i & 15) * 4;
        int node = base + r;
        float4 vv = (node < n) ? ((const float4*)(in + (size_t)node * 64))[i & 15]
                               : make_float4(0.f, 0.f, 0.f, 0.f);
        xs[r][c4]     = to_tf32(vv.x);
        xs[r][c4 + 1] = to_tf32(vv.y);
        xs[r][c4 + 2] = to_tf32(vv.z);
        xs[r][c4 + 3] = to_tf32(vv.w);
    }
    // load W [64 k][64 n]
    for (int i = tid; i < 64 * 16; i += 256) {
        int r = i >> 4, c4 = (i & 15) * 4;
        float4 wv = ((const float4*)(W + (size_t)r * 64))[i & 15];
        ws[r][c4]     = to_tf32(wv.x);
        ws[r][c4 + 1] = to_tf32(wv.y);
        ws[r][c4 + 2] = to_tf32(wv.z);
        ws[r][c4 + 3] = to_tf32(wv.w);
    }
    __syncthreads();

    int r0 = (warp & 3) * 16;
    int c0 = (warp >> 2) * 32;
    float acc[4][4] = {};
    #pragma unroll
    for (int ks = 0; ks < 64; ks += 8) {
        uint32_t a0 = __float_as_uint(xs[r0 + (lane >> 2)][ks + (lane & 3)]);
        uint32_t a1 = __float_as_uint(xs[r0 + (lane >> 2) + 8][ks + (lane & 3)]);
        uint32_t a2 = __float_as_uint(xs[r0 + (lane >> 2)][ks + (lane & 3) + 4]);
        uint32_t a3 = __float_as_uint(xs[r0 + (lane >> 2) + 8][ks + (lane & 3) + 4]);
        #pragma unroll
        for (int nt = 0; nt < 4; nt++) {
            int nc = c0 + nt * 8;
            uint32_t b0 = __float_as_uint(ws[ks + (lane & 3)][nc + (lane >> 2)]);
            uint32_t b1 = __float_as_uint(ws[ks + (lane & 3) + 4][nc + (lane >> 2)]);
            mma_tf32(acc[nt][0], acc[nt][1], acc[nt][2], acc[nt][3], a0, a1, a2, a3, b0, b1);
        }
    }
    // epilogue: bias + fp16 store
    int rA = r0 + (lane >> 2), rB = rA + 8;
    #pragma unroll
    for (int nt = 0; nt < 4; nt++) {
        int c = c0 + nt * 8 + (lane & 3) * 2;
        float bx = B[c], by = B[c + 1];
        int nodeA = base + rA;
        if (nodeA < n) {
            *(__half2*)(out + (size_t)nodeA * ostride + c) =
                __floats2half2_rn(acc[nt][0] + bx, acc[nt][1] + by);
        }
        int nodeB = base + rB;
        if (nodeB < n) {
            *(__half2*)(out + (size_t)nodeB * ostride + c) =
                __floats2half2_rn(acc[nt][2] + bx, acc[nt][3] + by);
        }
    }
}

// -------- edge attention + aggregation: warp per destination node --------
// lane owns dims (2*lane, 2*lane+1); head = lane/4 (8 heads x 8 dims).
// Edge indices batch-loaded (one coalesced LDG per 32 edges) and shfl-broadcast.
template <int T>
__global__ void k_gather(int n) {
    int gw = (blockIdx.x * blockDim.x + threadIdx.x) >> 5;
    int lane = threadIdx.x & 31;
    if (gw >= n) return;
    int dst = gw;
    const float inv_sqrt_d = 0.3535533905932738f;  // 1/sqrt(8)
    float2 q2 = __half22float2(((const __half2*)(g_qh + (size_t)dst * 64))[lane]);
    float did = g_dinv[dst];
    int e0 = g_off[dst], e1 = g_off[dst + 1];
    int tot = e1 - e0 + 1;                 // + self-loop
    float2 acc = make_float2(0.f, 0.f);
    for (int base = 0; base < tot; base += 32) {
        int idx = e0 + base + lane;
        int mysrc = (idx < e1) ? g_src[idx] : dst;   // idx==e1 -> self-loop
        int cnt = min(32, tot - base);
        for (int j = 0; j < cnt; j++) {
            int src = __shfl_sync(0xffffffffu, mysrc, j);
            float sdi = g_dinv[src];
            const __half2* kp = (const __half2*)(g_kh + (size_t)src * 192);
            const __half2* vp = (const __half2*)(g_vh + (size_t)src * 192);
            float2 kk[T], vv[T];
            #pragma unroll
            for (int s = 0; s < T; s++) {
                kk[s] = __half22float2(kp[s * 32 + lane]);
                vv[s] = __half22float2(vp[s * 32 + lane]);
            }
            float sc[T];
            float mx = -1e30f;
            #pragma unroll
            for (int s = 0; s < T; s++) {
                float p = q2.x * kk[s].x + q2.y * kk[s].y;
                p += __shfl_xor_sync(0xffffffffu, p, 1);
                p += __shfl_xor_sync(0xffffffffu, p, 2);   // head-group (4 lanes) dot
                sc[s] = p * inv_sqrt_d;
                mx = fmaxf(mx, sc[s]);
            }
            float sum = 0.f;
            #pragma unroll
            for (int s = 0; s < T; s++) { sc[s] = __expf(sc[s] - mx); sum += sc[s]; }
            float scale = __fdividef(sdi, sum);
            float2 m = make_float2(0.f, 0.f);
            #pragma unroll
            for (int s = 0; s < T; s++) { m.x += sc[s] * vv[s].x; m.y += sc[s] * vv[s].y; }
            acc.x += m.x * scale;
            acc.y += m.y * scale;
        }
    }
    float2 o;
    o.x = fmaxf(acc.x * did, 0.f);
    o.y = fmaxf(acc.y * did, 0.f);
    ((float2*)(g_x[T] + (size_t)dst * 64))[lane] = o;
}

// ---------------- lin2 + log_softmax: warp per node, reads g_x[3] ----------------
__global__ void k_lin2_ls(const float* __restrict__ W, const float* __restrict__ b,
                          float* __restrict__ out, int n) {
    int gw = (blockIdx.x * blockDim.x + threadIdx.x) >> 5;
    int lane = threadIdx.x & 31;
    if (gw >= n) return;
    const float* hr = g_x[3] + (size_t)gw * 64;
    float2 acc = ((const float2*)b)[lane];
    #pragma unroll 8
    for (int k = 0; k < 64; k++) {
        float hk = hr[k];
        float2 w2 = ((const float2*)(W + k * 64))[lane];
        acc.x += hk * w2.x;
        acc.y += hk * w2.y;
    }
    float m = fmaxf(acc.x, acc.y);
    #pragma unroll
    for (int o = 16; o > 0; o >>= 1) m = fmaxf(m, __shfl_xor_sync(0xffffffffu, m, o));
    float se = __expf(acc.x - m) + __expf(acc.y - m);
    #pragma unroll
    for (int o = 16; o > 0; o >>= 1) se += __shfl_xor_sync(0xffffffffu, se, o);
    float lse = m + logf(se);
    float2 r;
    r.x = acc.x - lse;
    r.y = acc.y - lse;
    ((float2*)(out + (size_t)gw * 64))[lane] = r;
}

// ---------------- host launcher (kernel launches ONLY) ----------------
extern "C" void kernel_launch(void* const* d_in, const int* in_sizes, int n_in,
                              void* d_out, int out_size) {
    const float* x  = (const float*)d_in[0];
    const int*   ei = (const int*)d_in[1];     // int32 (JAX default int without x64)
    const float* w1 = (const float*)d_in[2];
    const float* b1 = (const float*)d_in[3];
    const float* wq = (const float*)d_in[4];
    const float* bq = (const float*)d_in[5];
    const float* wk = (const float*)d_in[6];
    const float* bk = (const float*)d_in[7];
    const float* wv = (const float*)d_in[8];
    const float* bv = (const float*)d_in[9];
    const float* w2 = (const float*)d_in[10];
    const float* b2 = (const float*)d_in[11];

    int n = in_sizes[0] / 256;   // IN_C = 256
    int E = in_sizes[1] / 2;

    // CSR by destination (+ degrees/dinv)
    k_zero<<<(n + 255) / 256, 256>>>(n);
    k_hist<<<(E + 255) / 256, 256>>>(ei, E);
    k_scan<<<1, 1024>>>(n);
    k_scatter<<<(E + 255) / 256, 256>>>(ei, E);

    int gB64 = (n + 63) / 64;
    int gWarp = (n * 32 + 255) / 256;

    // input projection -> g_x[0]
    k_lin1<<<gB64, 256>>>(x, w1, b1, n);

    for (int l = 0; l < 3; l++) {
        int t = l + 1;
        dim3 grid(gB64, 2 * t + 1);
        k_qkv<<<grid, 256>>>(wq + l * 4096, bq + l * 64,
                             wk + l * 4096, bk + l * 64,
                             wv + l * 4096, bv + l * 64, t, n);
        if (t == 1)      k_gather<1><<<gWarp, 256>>>(n);
        else if (t == 2) k_gather<2><<<gWarp, 256>>>(n);
        else             k_gather<3><<<gWarp, 256>>>(n);
    }

    k_lin2_ls<<<gWarp, 256>>>(w2, b2, (float*)d_out, n);
}

// round 15
// speedup vs baseline: 2.1842x; 1.0760x over previous
#include <cuda_runtime.h>
#include <cuda_fp16.h>
#include <stdint.h>
#include <math.h>

#define MAXN 20000
#define MAXE 320000

// ---- scratch (static device globals; referenced ONLY from device code) ----
__device__ float  g_x[4][MAXN * 64];   // x_all slices: h, out1, out2, out3 (fp32)
__device__ __half g_qh[MAXN * 64];
// interleaved k/v: [node][slice(3)][pair(32)] -> uint2 {k2p,k2p+1 | v2p,v2p+1} (fp16)
__device__ uint2  g_kv[MAXN * 96];
__device__ int    g_cnt[MAXN];
__device__ int    g_cur[MAXN];
__device__ int    g_off[MAXN + 1];
__device__ float  g_dinv[MAXN];
__device__ int    g_src[MAXE];

__device__ __forceinline__ float to_tf32(float x) {
    uint32_t u;
    asm("cvt.rna.tf32.f32 %0, %1;" : "=r"(u) : "f"(x));
    return __uint_as_float(u);
}

__device__ __forceinline__ void mma_tf32(float& d0, float& d1, float& d2, float& d3,
                                         uint32_t a0, uint32_t a1, uint32_t a2, uint32_t a3,
                                         uint32_t b0, uint32_t b1) {
    asm("mma.sync.aligned.m16n8k8.row.col.f32.tf32.tf32.f32 "
        "{%0,%1,%2,%3}, {%4,%5,%6,%7}, {%8,%9}, {%0,%1,%2,%3};"
        : "+f"(d0), "+f"(d1), "+f"(d2), "+f"(d3)
        : "r"(a0), "r"(a1), "r"(a2), "r"(a3), "r"(b0), "r"(b1));
}

// ---------------- CSR build ----------------
__global__ void k_zero(int n) {
    int i = blockIdx.x * blockDim.x + threadIdx.x;
    if (i < n) g_cnt[i] = 0;
}

__global__ void k_hist(const int* __restrict__ ei, int E) {
    int e = blockIdx.x * blockDim.x + threadIdx.x;
    if (e < E) atomicAdd(&g_cnt[ei[E + e]], 1);
}

// single-block exclusive scan of g_cnt -> g_off (+ cursor copy, + dinv)
__global__ void k_scan(int n) {
    __shared__ int ssum[1024];
    int tid = threadIdx.x;
    int chunk = (n + 1023) >> 10;
    int beg = tid * chunk;
    int end = min(beg + chunk, n);
    int s = 0;
    for (int i = beg; i < end; i++) s += g_cnt[i];
    ssum[tid] = s;
    __syncthreads();
    for (int d = 1; d < 1024; d <<= 1) {
        int v = (tid >= d) ? ssum[tid - d] : 0;
        __syncthreads();
        ssum[tid] += v;
        __syncthreads();
    }
    int run = ssum[tid] - s;   // exclusive prefix
    for (int i = beg; i < end; i++) {
        g_off[i] = run;
        g_cur[i] = run;
        g_dinv[i] = rsqrtf((float)(g_cnt[i] + 1));  // +1 self-loop
        run += g_cnt[i];
    }
    if (tid == 1023) g_off[n] = ssum[1023];
}

__global__ void k_scatter(const int* __restrict__ ei, int E) {
    int e = blockIdx.x * blockDim.x + threadIdx.x;
    if (e < E) {
        int dst = ei[E + e];
        int p = atomicAdd(&g_cur[dst], 1);
        g_src[p] = ei[e];
    }
}

// ---------------- lin1 via tf32 mma: g_x[0] = relu(x @ W1 + b1), 256->64 ----------------
__global__ void k_lin1(const float* __restrict__ x, const float* __restrict__ W,
                       const float* __restrict__ b, int n) {
    __shared__ float xs[64][68];
    __shared__ float ws[64][68];
    int tid = threadIdx.x;
    int warp = tid >> 5, lane = tid & 31;
    int base = blockIdx.x * 64;
    int r0 = (warp & 3) * 16;        // warp row tile
    int c0 = (warp >> 2) * 32;       // warp col tile
    float acc[4][4] = {};

    for (int kc = 0; kc < 4; kc++) {         // K chunks of 64
        for (int i = tid; i < 64 * 16; i += 256) {
            int r = i >> 4, c4 = (i & 15) * 4;
            int node = base + r;
            float4 vv = (node < n) ? ((const float4*)(x + (size_t)node * 256 + kc * 64))[i & 15]
                                   : make_float4(0.f, 0.f, 0.f, 0.f);
            xs[r][c4]     = to_tf32(vv.x);
            xs[r][c4 + 1] = to_tf32(vv.y);
            xs[r][c4 + 2] = to_tf32(vv.z);
            xs[r][c4 + 3] = to_tf32(vv.w);
        }
        for (int i = tid; i < 64 * 16; i += 256) {
            int r = i >> 4, c4 = (i & 15) * 4;
            float4 wv = ((const float4*)(W + (size_t)(kc * 64 + r) * 64))[i & 15];
            ws[r][c4]     = to_tf32(wv.x);
            ws[r][c4 + 1] = to_tf32(wv.y);
            ws[r][c4 + 2] = to_tf32(wv.z);
            ws[r][c4 + 3] = to_tf32(wv.w);
        }
        __syncthreads();
        #pragma unroll
        for (int ks = 0; ks < 64; ks += 8) {
            uint32_t a0 = __float_as_uint(xs[r0 + (lane >> 2)][ks + (lane & 3)]);
            uint32_t a1 = __float_as_uint(xs[r0 + (lane >> 2) + 8][ks + (lane & 3)]);
            uint32_t a2 = __float_as_uint(xs[r0 + (lane >> 2)][ks + (lane & 3) + 4]);
            uint32_t a3 = __float_as_uint(xs[r0 + (lane >> 2) + 8][ks + (lane & 3) + 4]);
            #pragma unroll
            for (int nt = 0; nt < 4; nt++) {
                int nc = c0 + nt * 8;
                uint32_t b0 = __float_as_uint(ws[ks + (lane & 3)][nc + (lane >> 2)]);
                uint32_t b1 = __float_as_uint(ws[ks + (lane & 3) + 4][nc + (lane >> 2)]);
                mma_tf32(acc[nt][0], acc[nt][1], acc[nt][2], acc[nt][3], a0, a1, a2, a3, b0, b1);
            }
        }
        __syncthreads();
    }
    int rA = r0 + (lane >> 2), rB = rA + 8;
    #pragma unroll
    for (int nt = 0; nt < 4; nt++) {
        int c = c0 + nt * 8 + (lane & 3) * 2;
        float bx = b[c], by = b[c + 1];
        int nodeA = base + rA;
        if (nodeA < n) {
            float2 o = make_float2(fmaxf(acc[nt][0] + bx, 0.f), fmaxf(acc[nt][1] + by, 0.f));
            *(float2*)(g_x[0] + (size_t)nodeA * 64 + c) = o;
        }
        int nodeB = base + rB;
        if (nodeB < n) {
            float2 o = make_float2(fmaxf(acc[nt][2] + bx, 0.f), fmaxf(acc[nt][3] + by, 0.f));
            *(float2*)(g_x[0] + (size_t)nodeB * 64 + c) = o;
        }
    }
}

// ------- per-layer QKV projections via tf32 mma, one launch -------
// grid = (ceil(n/64), 2T+1). blockIdx.y: 0 -> Q; 1..T -> K_{y-1}; T+1..2T -> V_{y-T-1}
// K/V write into interleaved g_kv: half offset = node*384 + s*128 + (c/2)*4 + (K?0:2)
__global__ void k_qkv(const float* __restrict__ Wq, const float* __restrict__ Bq,
                      const float* __restrict__ Wk, const float* __restrict__ Bk,
                      const float* __restrict__ Wv, const float* __restrict__ Bv,
                      int T, int n) {
    __shared__ float xs[64][68];
    __shared__ float ws[64][68];
    int tid = threadIdx.x;
    int warp = tid >> 5, lane = tid & 31;
    int base = blockIdx.x * 64;
    int job = blockIdx.y;

    const float* W; const float* B; const float* in;
    __half* out; int ostride; int kvsel = -1;   // -1: q, 0: k, 2: v
    if (job == 0) {
        W = Wq; B = Bq; in = g_x[T - 1];
        out = g_qh; ostride = 64;
    } else if (job <= T) {
        W = Wk; B = Bk; in = g_x[job - 1];
        out = (__half*)g_kv + (job - 1) * 128; ostride = 384; kvsel = 0;
    } else {
        W = Wv; B = Bv; in = g_x[job - T - 1];
        out = (__half*)g_kv + (job - T - 1) * 128; ostride = 384; kvsel = 2;
    }

    for (int i = tid; i < 64 * 16; i += 256) {
        int r = i >> 4, c4 = (i & 15) * 4;
        int node = base + r;
        float4 vv = (node < n) ? ((const float4*)(in + (size_t)node * 64))[i & 15]
                               : make_float4(0.f, 0.f, 0.f, 0.f);
        xs[r][c4]     = to_tf32(vv.x);
        xs[r][c4 + 1] = to_tf32(vv.y);
        xs[r][c4 + 2] = to_tf32(vv.z);
        xs[r][c4 + 3] = to_tf32(vv.w);
    }
    for (int i = tid; i < 64 * 16; i += 256) {
        int r = i >> 4, c4 = (i & 15) * 4;
        float4 wv = ((const float4*)(W + (size_t)r * 64))[i & 15];
        ws[r][c4]     = to_tf32(wv.x);
        ws[r][c4 + 1] = to_tf32(wv.y);
        ws[r][c4 + 2] = to_tf32(wv.z);
        ws[r][c4 + 3] = to_tf32(wv.w);
    }
    __syncthreads();

    int r0 = (warp & 3) * 16;
    int c0 = (warp >> 2) * 32;
    float acc[4][4] = {};
    #pragma unroll
    for (int ks = 0; ks < 64; ks += 8) {
        uint32_t a0 = __float_as_uint(xs[r0 + (lane >> 2)][ks + (lane & 3)]);
        uint32_t a1 = __float_as_uint(xs[r0 + (lane >> 2) + 8][ks + (lane & 3)]);
        uint32_t a2 = __float_as_uint(xs[r0 + (lane >> 2)][ks + (lane & 3) + 4]);
        uint32_t a3 = __float_as_uint(xs[r0 + (lane >> 2) + 8][ks + (lane & 3) + 4]);
        #pragma unroll
        for (int nt = 0; nt < 4; nt++) {
            int nc = c0 + nt * 8;
            uint32_t b0 = __float_as_uint(ws[ks + (lane & 3)][nc + (lane >> 2)]);
            uint32_t b1 = __float_as_uint(ws[ks + (lane & 3) + 4][nc + (lane >> 2)]);
            mma_tf32(acc[nt][0], acc[nt][1], acc[nt][2], acc[nt][3], a0, a1, a2, a3, b0, b1);
        }
    }
    // epilogue: bias + fp16 store (q flat; k/v interleaved)
    int rA = r0 + (lane >> 2), rB = rA + 8;
    #pragma unroll
    for (int nt = 0; nt < 4; nt++) {
        int c = c0 + nt * 8 + (lane & 3) * 2;    // even
        float bx = B[c], by = B[c + 1];
        int coff = (kvsel < 0) ? c : ((c >> 1) << 2) + kvsel;
        int nodeA = base + rA;
        if (nodeA < n) {
            *(__half2*)(out + (size_t)nodeA * ostride + coff) =
                __floats2half2_rn(acc[nt][0] + bx, acc[nt][1] + by);
        }
        int nodeB = base + rB;
        if (nodeB < n) {
            *(__half2*)(out + (size_t)nodeB * ostride + coff) =
                __floats2half2_rn(acc[nt][2] + bx, acc[nt][3] + by);
        }
    }
}

// -------- edge attention + aggregation: warp per destination node --------
// lane owns dim-pair p=lane (dims 2p,2p+1); head = lane/4 (8 heads x 8 dims).
// Edge indices AND source dinv batch-loaded coalesced (1 LDG + 1 LDG per 32 edges),
// broadcast via shfl. One uint2 LDG per slice fetches k AND v half2s together.
template <int T>
__global__ void k_gather(int n) {
    int gw = (blockIdx.x * blockDim.x + threadIdx.x) >> 5;
    int lane = threadIdx.x & 31;
    if (gw >= n) return;
    int dst = gw;
    const float inv_sqrt_d = 0.3535533905932738f;  // 1/sqrt(8)
    float2 q2 = __half22float2(((const __half2*)(g_qh + (size_t)dst * 64))[lane]);
    float did = g_dinv[dst];
    int e0 = g_off[dst], e1 = g_off[dst + 1];
    int tot = e1 - e0 + 1;                 // + self-loop
    float2 acc = make_float2(0.f, 0.f);
    for (int base = 0; base < tot; base += 32) {
        int idx = e0 + base + lane;
        int mysrc = (idx < e1) ? g_src[idx] : dst;   // idx==e1 -> self-loop
        float mydinv = g_dinv[mysrc];
        int cnt = min(32, tot - base);
        for (int j = 0; j < cnt; j++) {
            int src = __shfl_sync(0xffffffffu, mysrc, j);
            float sdi = __shfl_sync(0xffffffffu, mydinv, j);
            const uint2* kvp = g_kv + (size_t)src * 96 + lane;
            float2 kk[T], vv[T];
            #pragma unroll
            for (int s = 0; s < T; s++) {
                uint2 u = kvp[s * 32];
                kk[s] = __half22float2(*(const __half2*)&u.x);
                vv[s] = __half22float2(*(const __half2*)&u.y);
            }
            float sc[T];
            float mx = -1e30f;
            #pragma unroll
            for (int s = 0; s < T; s++) {
                float p = q2.x * kk[s].x + q2.y * kk[s].y;
                p += __shfl_xor_sync(0xffffffffu, p, 1);
                p += __shfl_xor_sync(0xffffffffu, p, 2);   // head-group (4 lanes) dot
                sc[s] = p * inv_sqrt_d;
                mx = fmaxf(mx, sc[s]);
            }
            float sum = 0.f;
            #pragma unroll
            for (int s = 0; s < T; s++) { sc[s] = __expf(sc[s] - mx); sum += sc[s]; }
            float scale = __fdividef(sdi, sum);
            float2 m = make_float2(0.f, 0.f);
            #pragma unroll
            for (int s = 0; s < T; s++) { m.x += sc[s] * vv[s].x; m.y += sc[s] * vv[s].y; }
            acc.x += m.x * scale;
            acc.y += m.y * scale;
        }
    }
    float2 o;
    o.x = fmaxf(acc.x * did, 0.f);
    o.y = fmaxf(acc.y * did, 0.f);
    ((float2*)(g_x[T] + (size_t)dst * 64))[lane] = o;
}

// ---------------- lin2 + log_softmax: warp per node, reads g_x[3] ----------------
__global__ void k_lin2_ls(const float* __restrict__ W, const float* __restrict__ b,
                          float* __restrict__ out, int n) {
    int gw = (blockIdx.x * blockDim.x + threadIdx.x) >> 5;
    int lane = threadIdx.x & 31;
    if (gw >= n) return;
    const float* hr = g_x[3] + (size_t)gw * 64;
    float2 acc = ((const float2*)b)[lane];
    #pragma unroll 8
    for (int k = 0; k < 64; k++) {
        float hk = hr[k];
        float2 w2 = ((const float2*)(W + k * 64))[lane];
        acc.x += hk * w2.x;
        acc.y += hk * w2.y;
    }
    float m = fmaxf(acc.x, acc.y);
    #pragma unroll
    for (int o = 16; o > 0; o >>= 1) m = fmaxf(m, __shfl_xor_sync(0xffffffffu, m, o));
    float se = __expf(acc.x - m) + __expf(acc.y - m);
    #pragma unroll
    for (int o = 16; o > 0; o >>= 1) se += __shfl_xor_sync(0xffffffffu, se, o);
    float lse = m + logf(se);
    float2 r;
    r.x = acc.x - lse;
    r.y = acc.y - lse;
    ((float2*)(out + (size_t)gw * 64))[lane] = r;
}

// ---------------- host launcher (kernel launches ONLY) ----------------
extern "C" void kernel_launch(void* const* d_in, const int* in_sizes, int n_in,
                              void* d_out, int out_size) {
    const float* x  = (const float*)d_in[0];
    const int*   ei = (const int*)d_in[1];     // int32 (JAX default int without x64)
    const float* w1 = (const float*)d_in[2];
    const float* b1 = (const float*)d_in[3];
    const float* wq = (const float*)d_in[4];
    const float* bq = (const float*)d_in[5];
    const float* wk = (const float*)d_in[6];
    const float* bk = (const float*)d_in[7];
    const float* wv = (const float*)d_in[8];
    const float* bv = (const float*)d_in[9];
    const float* w2 = (const float*)d_in[10];
    const float* b2 = (const float*)d_in[11];

    int n = in_sizes[0] / 256;   // IN_C = 256
    int E = in_sizes[1] / 2;

    // CSR by destination (+ degrees/dinv)
    k_zero<<<(n + 255) / 256, 256>>>(n);
    k_hist<<<(E + 255) / 256, 256>>>(ei, E);
    k_scan<<<1, 1024>>>(n);
    k_scatter<<<(E + 255) / 256, 256>>>(ei, E);

    int gB64 = (n + 63) / 64;
    int gWarp = (n * 32 + 255) / 256;

    // input projection -> g_x[0]
    k_lin1<<<gB64, 256>>>(x, w1, b1, n);

    for (int l = 0; l < 3; l++) {
        int t = l + 1;
        dim3 grid(gB64, 2 * t + 1);
        k_qkv<<<grid, 256>>>(wq + l * 4096, bq + l * 64,
                             wk + l * 4096, bk + l * 64,
                             wv + l * 4096, bv + l * 64, t, n);
        if (t == 1)      k_gather<1><<<gWarp, 256>>>(n);
        else if (t == 2) k_gather<2><<<gWarp, 256>>>(n);
        else             k_gather<3><<<gWarp, 256>>>(n);
    }

    k_lin2_ls<<<gWarp, 256>>>(w2, b2, (float*)d_out, n);
}

// round 16
// speedup vs baseline: 2.3016x; 1.0537x over previous
#include <cuda_runtime.h>
#include <cuda_fp16.h>
#include <stdint.h>
#include <math.h>

#define MAXN 20000
#define MAXE 320000

// ---- scratch (static device globals; referenced ONLY from device code) ----
__device__ float  g_x[4][MAXN * 64];   // x_all slices: h, out1, out2, out3 (fp32)
__device__ __half g_qh[MAXN * 64];     // layer>=2: q; layer 1: v (flat)
// interleaved k/v: [node][slice(3)][pair(32)] -> uint2 {k2p,k2p+1 | v2p,v2p+1} (fp16)
__device__ uint2  g_kv[MAXN * 96];
__device__ int    g_cnt[MAXN];
__device__ int    g_cur[MAXN];
__device__ int    g_off[MAXN + 1];
__device__ float  g_dinv[MAXN];
__device__ int    g_src[MAXE];

__device__ __forceinline__ float to_tf32(float x) {
    uint32_t u;
    asm("cvt.rna.tf32.f32 %0, %1;" : "=r"(u) : "f"(x));
    return __uint_as_float(u);
}

__device__ __forceinline__ void mma_tf32(float& d0, float& d1, float& d2, float& d3,
                                         uint32_t a0, uint32_t a1, uint32_t a2, uint32_t a3,
                                         uint32_t b0, uint32_t b1) {
    asm("mma.sync.aligned.m16n8k8.row.col.f32.tf32.tf32.f32 "
        "{%0,%1,%2,%3}, {%4,%5,%6,%7}, {%8,%9}, {%0,%1,%2,%3};"
        : "+f"(d0), "+f"(d1), "+f"(d2), "+f"(d3)
        : "r"(a0), "r"(a1), "r"(a2), "r"(a3), "r"(b0), "r"(b1));
}

// ---------------- CSR build ----------------
__global__ void k_zero(int n) {
    int i = blockIdx.x * blockDim.x + threadIdx.x;
    if (i < n) g_cnt[i] = 0;
}

__global__ void k_hist(const int* __restrict__ ei, int E) {
    int e = blockIdx.x * blockDim.x + threadIdx.x;
    if (e < E) atomicAdd(&g_cnt[ei[E + e]], 1);
}

// single-block exclusive scan of g_cnt -> g_off (+ cursor copy, + dinv)
__global__ void k_scan(int n) {
    __shared__ int ssum[1024];
    int tid = threadIdx.x;
    int chunk = (n + 1023) >> 10;
    int beg = tid * chunk;
    int end = min(beg + chunk, n);
    int s = 0;
    for (int i = beg; i < end; i++) s += g_cnt[i];
    ssum[tid] = s;
    __syncthreads();
    for (int d = 1; d < 1024; d <<= 1) {
        int v = (tid >= d) ? ssum[tid - d] : 0;
        __syncthreads();
        ssum[tid] += v;
        __syncthreads();
    }
    int run = ssum[tid] - s;   // exclusive prefix
    for (int i = beg; i < end; i++) {
        g_off[i] = run;
        g_cur[i] = run;
        g_dinv[i] = rsqrtf((float)(g_cnt[i] + 1));  // +1 self-loop
        run += g_cnt[i];
    }
    if (tid == 1023) g_off[n] = ssum[1023];
}

__global__ void k_scatter(const int* __restrict__ ei, int E) {
    int e = blockIdx.x * blockDim.x + threadIdx.x;
    if (e < E) {
        int dst = ei[E + e];
        int p = atomicAdd(&g_cur[dst], 1);
        g_src[p] = ei[e];
    }
}

// ---------------- lin1 via tf32 mma: g_x[0] = relu(x @ W1 + b1), 256->64 ----------------
__global__ void k_lin1(const float* __restrict__ x, const float* __restrict__ W,
                       const float* __restrict__ b, int n) {
    __shared__ float xs[64][68];
    __shared__ float ws[64][68];
    int tid = threadIdx.x;
    int warp = tid >> 5, lane = tid & 31;
    int base = blockIdx.x * 64;
    int r0 = (warp & 3) * 16;        // warp row tile
    int c0 = (warp >> 2) * 32;       // warp col tile
    float acc[4][4] = {};

    for (int kc = 0; kc < 4; kc++) {         // K chunks of 64
        for (int i = tid; i < 64 * 16; i += 256) {
            int r = i >> 4, c4 = (i & 15) * 4;
            int node = base + r;
            float4 vv = (node < n) ? ((const float4*)(x + (size_t)node * 256 + kc * 64))[i & 15]
                                   : make_float4(0.f, 0.f, 0.f, 0.f);
            xs[r][c4]     = to_tf32(vv.x);
            xs[r][c4 + 1] = to_tf32(vv.y);
            xs[r][c4 + 2] = to_tf32(vv.z);
            xs[r][c4 + 3] = to_tf32(vv.w);
        }
        for (int i = tid; i < 64 * 16; i += 256) {
            int r = i >> 4, c4 = (i & 15) * 4;
            float4 wv = ((const float4*)(W + (size_t)(kc * 64 + r) * 64))[i & 15];
            ws[r][c4]     = to_tf32(wv.x);
            ws[r][c4 + 1] = to_tf32(wv.y);
            ws[r][c4 + 2] = to_tf32(wv.z);
            ws[r][c4 + 3] = to_tf32(wv.w);
        }
        __syncthreads();
        #pragma unroll
        for (int ks = 0; ks < 64; ks += 8) {
            uint32_t a0 = __float_as_uint(xs[r0 + (lane >> 2)][ks + (lane & 3)]);
            uint32_t a1 = __float_as_uint(xs[r0 + (lane >> 2) + 8][ks + (lane & 3)]);
            uint32_t a2 = __float_as_uint(xs[r0 + (lane >> 2)][ks + (lane & 3) + 4]);
            uint32_t a3 = __float_as_uint(xs[r0 + (lane >> 2) + 8][ks + (lane & 3) + 4]);
            #pragma unroll
            for (int nt = 0; nt < 4; nt++) {
                int nc = c0 + nt * 8;
                uint32_t b0 = __float_as_uint(ws[ks + (lane & 3)][nc + (lane >> 2)]);
                uint32_t b1 = __float_as_uint(ws[ks + (lane & 3) + 4][nc + (lane >> 2)]);
                mma_tf32(acc[nt][0], acc[nt][1], acc[nt][2], acc[nt][3], a0, a1, a2, a3, b0, b1);
            }
        }
        __syncthreads();
    }
    int rA = r0 + (lane >> 2), rB = rA + 8;
    #pragma unroll
    for (int nt = 0; nt < 4; nt++) {
        int c = c0 + nt * 8 + (lane & 3) * 2;
        float bx = b[c], by = b[c + 1];
        int nodeA = base + rA;
        if (nodeA < n) {
            float2 o = make_float2(fmaxf(acc[nt][0] + bx, 0.f), fmaxf(acc[nt][1] + by, 0.f));
            *(float2*)(g_x[0] + (size_t)nodeA * 64 + c) = o;
        }
        int nodeB = base + rB;
        if (nodeB < n) {
            float2 o = make_float2(fmaxf(acc[nt][2] + bx, 0.f), fmaxf(acc[nt][3] + by, 0.f));
            *(float2*)(g_x[0] + (size_t)nodeB * 64 + c) = o;
        }
    }
}

// ------- per-layer QKV projections via tf32 mma, one launch -------
// mode 0 (layers 2,3): grid.y = 2T+1; job 0 -> Q (flat g_qh);
//                      1..T -> K_{y-1} (interleaved); T+1..2T -> V_{y-T-1} (interleaved)
// mode 1 (layer 1):    grid.y = 1; job 0 -> V from g_x[0], written FLAT into g_qh
__global__ void k_qkv(const float* __restrict__ Wq, const float* __restrict__ Bq,
                      const float* __restrict__ Wk, const float* __restrict__ Bk,
                      const float* __restrict__ Wv, const float* __restrict__ Bv,
                      int T, int n, int mode) {
    __shared__ float xs[64][68];
    __shared__ float ws[64][68];
    int tid = threadIdx.x;
    int warp = tid >> 5, lane = tid & 31;
    int base = blockIdx.x * 64;
    int job = blockIdx.y;

    const float* W; const float* B; const float* in;
    __half* out; int ostride; int kvsel = -1;   // -1: flat, 0: k slot, 2: v slot
    if (mode == 1) {
        W = Wv; B = Bv; in = g_x[0];
        out = g_qh; ostride = 64;
    } else if (job == 0) {
        W = Wq; B = Bq; in = g_x[T - 1];
        out = g_qh; ostride = 64;
    } else if (job <= T) {
        W = Wk; B = Bk; in = g_x[job - 1];
        out = (__half*)g_kv + (job - 1) * 128; ostride = 384; kvsel = 0;
    } else {
        W = Wv; B = Bv; in = g_x[job - T - 1];
        out = (__half*)g_kv + (job - T - 1) * 128; ostride = 384; kvsel = 2;
    }

    for (int i = tid; i < 64 * 16; i += 256) {
        int r = i >> 4, c4 = (i & 15) * 4;
        int node = base + r;
        float4 vv = (node < n) ? ((const float4*)(in + (size_t)node * 64))[i & 15]
                               : make_float4(0.f, 0.f, 0.f, 0.f);
        xs[r][c4]     = to_tf32(vv.x);
        xs[r][c4 + 1] = to_tf32(vv.y);
        xs[r][c4 + 2] = to_tf32(vv.z);
        xs[r][c4 + 3] = to_tf32(vv.w);
    }
    for (int i = tid; i < 64 * 16; i += 256) {
        int r = i >> 4, c4 = (i & 15) * 4;
        float4 wv = ((const float4*)(W + (size_t)r * 64))[i & 15];
        ws[r][c4]     = to_tf32(wv.x);
        ws[r][c4 + 1] = to_tf32(wv.y);
        ws[r][c4 + 2] = to_tf32(wv.z);
        ws[r][c4 + 3] = to_tf32(wv.w);
    }
    __syncthreads();

    int r0 = (warp & 3) * 16;
    int c0 = (warp >> 2) * 32;
    float acc[4][4] = {};
    #pragma unroll
    for (int ks = 0; ks < 64; ks += 8) {
        uint32_t a0 = __float_as_uint(xs[r0 + (lane >> 2)][ks + (lane & 3)]);
        uint32_t a1 = __float_as_uint(xs[r0 + (lane >> 2) + 8][ks + (lane & 3)]);
        uint32_t a2 = __float_as_uint(xs[r0 + (lane >> 2)][ks + (lane & 3) + 4]);
        uint32_t a3 = __float_as_uint(xs[r0 + (lane >> 2) + 8][ks + (lane & 3) + 4]);
        #pragma unroll
        for (int nt = 0; nt < 4; nt++) {
            int nc = c0 + nt * 8;
            uint32_t b0 = __float_as_uint(ws[ks + (lane & 3)][nc + (lane >> 2)]);
            uint32_t b1 = __float_as_uint(ws[ks + (lane & 3) + 4][nc + (lane >> 2)]);
            mma_tf32(acc[nt][0], acc[nt][1], acc[nt][2], acc[nt][3], a0, a1, a2, a3, b0, b1);
        }
    }
    // epilogue: bias + fp16 store (flat or interleaved)
    int rA = r0 + (lane >> 2), rB = rA + 8;
    #pragma unroll
    for (int nt = 0; nt < 4; nt++) {
        int c = c0 + nt * 8 + (lane & 3) * 2;    // even
        float bx = B[c], by = B[c + 1];
        int coff = (kvsel < 0) ? c : ((c >> 1) << 2) + kvsel;
        int nodeA = base + rA;
        if (nodeA < n) {
            *(__half2*)(out + (size_t)nodeA * ostride + coff) =
                __floats2half2_rn(acc[nt][0] + bx, acc[nt][1] + by);
        }
        int nodeB = base + rB;
        if (nodeB < n) {
            *(__half2*)(out + (size_t)nodeB * ostride + coff) =
                __floats2half2_rn(acc[nt][2] + bx, acc[nt][3] + by);
        }
    }
}

// -------- layer-1 aggregation: attn==1 (softmax over 1 element) --------
// out1 = relu(dinv[dst] * sum_src dinv[src] * v[src]); v flat in g_qh.
__global__ void k_gather1(int n) {
    int gw = (blockIdx.x * blockDim.x + threadIdx.x) >> 5;
    int lane = threadIdx.x & 31;
    if (gw >= n) return;
    int dst = gw;
    float did = g_dinv[dst];
    int e0 = g_off[dst], e1 = g_off[dst + 1];
    int tot = e1 - e0 + 1;                 // + self-loop
    float2 acc = make_float2(0.f, 0.f);
    for (int base = 0; base < tot; base += 32) {
        int idx = e0 + base + lane;
        int mysrc = (idx < e1) ? g_src[idx] : dst;
        float mydinv = g_dinv[mysrc];
        int cnt = min(32, tot - base);
        for (int j = 0; j < cnt; j++) {
            int src = __shfl_sync(0xffffffffu, mysrc, j);
            float sdi = __shfl_sync(0xffffffffu, mydinv, j);
            float2 v2 = __half22float2(((const __half2*)(g_qh + (size_t)src * 64))[lane]);
            acc.x += v2.x * sdi;
            acc.y += v2.y * sdi;
        }
    }
    float2 o;
    o.x = fmaxf(acc.x * did, 0.f);
    o.y = fmaxf(acc.y * did, 0.f);
    ((float2*)(g_x[1] + (size_t)dst * 64))[lane] = o;
}

// -------- edge attention + aggregation (T>=2): warp per destination node --------
// lane owns dim-pair p=lane; head = lane/4. Prefetched kv, no-max softmax.
template <int T>
__global__ void k_gather(int n) {
    int gw = (blockIdx.x * blockDim.x + threadIdx.x) >> 5;
    int lane = threadIdx.x & 31;
    if (gw >= n) return;
    int dst = gw;
    const float inv_sqrt_d = 0.3535533905932738f;  // 1/sqrt(8)
    float2 q2 = __half22float2(((const __half2*)(g_qh + (size_t)dst * 64))[lane]);
    float did = g_dinv[dst];
    int e0 = g_off[dst], e1 = g_off[dst + 1];
    int tot = e1 - e0 + 1;                 // + self-loop
    float2 acc = make_float2(0.f, 0.f);
    for (int base = 0; base < tot; base += 32) {
        int idx = e0 + base + lane;
        int mysrc = (idx < e1) ? g_src[idx] : dst;
        float mydinv = g_dinv[mysrc];
        int cnt = min(32, tot - base);
        // prefetch edge 0
        uint2 u[T];
        {
            int s0 = __shfl_sync(0xffffffffu, mysrc, 0);
            const uint2* kvp = g_kv + (size_t)s0 * 96 + lane;
            #pragma unroll
            for (int s = 0; s < T; s++) u[s] = kvp[s * 32];
        }
        for (int j = 0; j < cnt; j++) {
            uint2 nx[T];
            if (j + 1 < cnt) {
                int s1 = __shfl_sync(0xffffffffu, mysrc, j + 1);
                const uint2* kvp = g_kv + (size_t)s1 * 96 + lane;
                #pragma unroll
                for (int s = 0; s < T; s++) nx[s] = kvp[s * 32];
            }
            float sdi = __shfl_sync(0xffffffffu, mydinv, j);
            float sc[T];
            float sum = 0.f;
            #pragma unroll
            for (int s = 0; s < T; s++) {
                float2 kk = __half22float2(*(const __half2*)&u[s].x);
                float p = q2.x * kk.x + q2.y * kk.y;
                p += __shfl_xor_sync(0xffffffffu, p, 1);
                p += __shfl_xor_sync(0xffffffffu, p, 2);   // head-group (4 lanes) dot
                sc[s] = __expf(p * inv_sqrt_d);            // no-max softmax (scores bounded)
                sum += sc[s];
            }
            float scale = __fdividef(sdi, sum);
            float2 m = make_float2(0.f, 0.f);
            #pragma unroll
            for (int s = 0; s < T; s++) {
                float2 vv = __half22float2(*(const __half2*)&u[s].y);
                m.x += sc[s] * vv.x;
                m.y += sc[s] * vv.y;
            }
            acc.x += m.x * scale;
            acc.y += m.y * scale;
            #pragma unroll
            for (int s = 0; s < T; s++) u[s] = nx[s];
        }
    }
    float2 o;
    o.x = fmaxf(acc.x * did, 0.f);
    o.y = fmaxf(acc.y * did, 0.f);
    ((float2*)(g_x[T] + (size_t)dst * 64))[lane] = o;
}

// ---------------- lin2 + log_softmax: warp per node, reads g_x[3] ----------------
__global__ void k_lin2_ls(const float* __restrict__ W, const float* __restrict__ b,
                          float* __restrict__ out, int n) {
    int gw = (blockIdx.x * blockDim.x + threadIdx.x) >> 5;
    int lane = threadIdx.x & 31;
    if (gw >= n) return;
    const float* hr = g_x[3] + (size_t)gw * 64;
    float2 acc = ((const float2*)b)[lane];
    #pragma unroll 8
    for (int k = 0; k < 64; k++) {
        float hk = hr[k];
        float2 w2 = ((const float2*)(W + k * 64))[lane];
        acc.x += hk * w2.x;
        acc.y += hk * w2.y;
    }
    float m = fmaxf(acc.x, acc.y);
    #pragma unroll
    for (int o = 16; o > 0; o >>= 1) m = fmaxf(m, __shfl_xor_sync(0xffffffffu, m, o));
    float se = __expf(acc.x - m) + __expf(acc.y - m);
    #pragma unroll
    for (int o = 16; o > 0; o >>= 1) se += __shfl_xor_sync(0xffffffffu, se, o);
    float lse = m + logf(se);
    float2 r;
    r.x = acc.x - lse;
    r.y = acc.y - lse;
    ((float2*)(out + (size_t)gw * 64))[lane] = r;
}

// ---------------- host launcher (kernel launches ONLY) ----------------
extern "C" void kernel_launch(void* const* d_in, const int* in_sizes, int n_in,
                              void* d_out, int out_size) {
    const float* x  = (const float*)d_in[0];
    const int*   ei = (const int*)d_in[1];     // int32 (JAX default int without x64)
    const float* w1 = (const float*)d_in[2];
    const float* b1 = (const float*)d_in[3];
    const float* wq = (const float*)d_in[4];
    const float* bq = (const float*)d_in[5];
    const float* wk = (const float*)d_in[6];
    const float* bk = (const float*)d_in[7];
    const float* wv = (const float*)d_in[8];
    const float* bv = (const float*)d_in[9];
    const float* w2 = (const float*)d_in[10];
    const float* b2 = (const float*)d_in[11];

    int n = in_sizes[0] / 256;   // IN_C = 256
    int E = in_sizes[1] / 2;

    // CSR by destination (+ degrees/dinv)
    k_zero<<<(n + 255) / 256, 256>>>(n);
    k_hist<<<(E + 255) / 256, 256>>>(ei, E);
    k_scan<<<1, 1024>>>(n);
    k_scatter<<<(E + 255) / 256, 256>>>(ei, E);

    int gB64 = (n + 63) / 64;
    int gWarp = (n * 32 + 255) / 256;

    // input projection -> g_x[0]
    k_lin1<<<gB64, 256>>>(x, w1, b1, n);

    // layer 1: attention is identity over single timestep -> V-only
    k_qkv<<<dim3(gB64, 1), 256>>>(wq, bq, wk, bk, wv, bv, 1, n, 1);
    k_gather1<<<gWarp, 256>>>(n);

    for (int l = 1; l < 3; l++) {
        int t = l + 1;
        dim3 grid(gB64, 2 * t + 1);
        k_qkv<<<grid, 256>>>(wq + l * 4096, bq + l * 64,
                             wk + l * 4096, bk + l * 64,
                             wv + l * 4096, bv + l * 64, t, n, 0);
        if (t == 2) k_gather<2><<<gWarp, 256>>>(n);
        else        k_gather<3><<<gWarp, 256>>>(n);
    }

    k_lin2_ls<<<gWarp, 256>>>(w2, b2, (float*)d_out, n);
}